// round 3
// baseline (speedup 1.0000x reference)
#include <cuda_runtime.h>
#include <cstdint>

// IMDCT fused (FFMA2 path, round 3):
//   out[b, s*256+k] = sum_f Ks[k,f]*spec[b,f,s] + sum_f Ks[k+256,f]*spec[b,f,s-1],  Ks = kernels/128
//
// Block = 128 threads; thread owns k = tid and k = tid+128, NSEG=32 segments.
// Spec columns s0-1..s0+32 in smem (broadcast LDS.v2.b64 feeds 8 packed FMAs each).
// Weights pre-transposed+pre-scaled into g_kt4[f2][k] = float4{wK(2f2),wB(2f2),wK(2f2+1),wB(2f2+1)}
// -> one LDG.128 per stream per TWO f's, prefetched 2 f-pairs ahead (hides L2 latency).

#define NFREQ      256
#define T_FRAMES   4096
#define NSEG       32
#define NCOL_PAD   36          // 34 used cols (33 real + 1 zero), padded for 16B loads
#define L_OUT      1048832
#define NSEG_TOTAL 4097
#define NF2        128         // f-pairs

#define FMA2(acc, a, v) \
    asm("fma.rn.f32x2 %0, %1, %2, %0;" : "+l"(acc) : "l"(a), "l"(v))
#define PACK2(dst, x) \
    asm("mov.b64 %0, {%1, %1};" : "=l"(dst) : "r"(__float_as_uint(x)))

// [NF2+2 rows x 256 k] float4; 2 pad rows so depth-2 prefetch stays in-bounds.
__device__ float4 g_kt4[(NF2 + 2) * 256];

__global__ void transpose_scale_kernel(const float* __restrict__ kernels)
{
    int idx = blockIdx.x * blockDim.x + threadIdx.x;   // 32768 threads
    int k  = idx & 255;                                // k fastest -> coalesced 16B stores
    int f2 = idx >> 8;                                 // 0..127
    const float s = 1.0f / 128.0f;
    float4 w;
    w.x = s * kernels[k * 256 + 2 * f2];
    w.y = s * kernels[(k + 256) * 256 + 2 * f2];
    w.z = s * kernels[k * 256 + 2 * f2 + 1];
    w.w = s * kernels[(k + 256) * 256 + 2 * f2 + 1];
    g_kt4[f2 * 256 + k] = w;
}

__global__ __launch_bounds__(128, 3)
void imdct_main_kernel(const float* __restrict__ spec, float* __restrict__ out)
{
    __shared__ float spec_sm[NFREQ * NCOL_PAD];        // 36,864 B

    const int tid = threadIdx.x;                       // 0..127
    const int b   = blockIdx.y;
    const int s0  = blockIdx.x * NSEG;

    // ---- Load spec columns c = s0-1 .. s0+32 (zero-fill edges / pad) ----
    const float* specB = spec + (size_t)b * NFREQ * T_FRAMES;
    for (int idx = tid; idx < NFREQ * NCOL_PAD; idx += 128) {
        int f = idx / NCOL_PAD;
        int j = idx - f * NCOL_PAD;
        int c = s0 - 1 + j;
        float v = 0.0f;
        if (j < 34 && c >= 0 && c < T_FRAMES)
            v = specB[(size_t)f * T_FRAMES + c];
        spec_sm[idx] = v;
    }
    __syncthreads();

    // ---- Accumulators ----
    // aK*: 17 pairs (segments jk=1..32 read pairs 0..16); aB*: 16 pairs (segments i=0..31
    // read pairs 0..15; pair 16 would target segs 33/34 -> dead, eliminated).
    unsigned long long aK0[17], aK1[17], aB0[16], aB1[16];
    #pragma unroll
    for (int p = 0; p < 17; p++) { aK0[p] = 0ull; aK1[p] = 0ull; }
    #pragma unroll
    for (int p = 0; p < 16; p++) { aB0[p] = 0ull; aB1[p] = 0ull; }

    const uint32_t sbase = (uint32_t)__cvta_generic_to_shared(spec_sm);
    const float4* __restrict__ w0p = g_kt4 + tid;          // stream k = tid
    const float4* __restrict__ w1p = g_kt4 + tid + 128;    // stream k = tid+128

    // Depth-2 prefetch pipeline over f-pairs.
    float4 c0 = w0p[0],   c1 = w1p[0];
    float4 n0 = w0p[256], n1 = w1p[256];

    #pragma unroll 2
    for (int j = 0; j < NF2; j++) {
        float4 p0 = w0p[(j + 2) * 256];                    // prefetch f-pair j+2
        float4 p1 = w1p[(j + 2) * 256];

        uint32_t srow = sbase + (uint32_t)(2 * j * (NCOL_PAD * 4));

        // ---- f0 = 2j ----
        {
            unsigned long long ka0, kb0, ka1, kb1;
            PACK2(ka0, c0.x); PACK2(kb0, c0.y);
            PACK2(ka1, c1.x); PACK2(kb1, c1.y);
            #pragma unroll
            for (int q = 0; q < 8; q++) {
                unsigned long long v01, v23;
                asm volatile("ld.shared.v2.b64 {%0, %1}, [%2];"
                             : "=l"(v01), "=l"(v23) : "r"(srow + q * 16));
                FMA2(aK0[2*q],     ka0, v01);
                FMA2(aK1[2*q],     ka1, v01);
                FMA2(aK0[2*q + 1], ka0, v23);
                FMA2(aK1[2*q + 1], ka1, v23);
                FMA2(aB0[2*q],     kb0, v01);
                FMA2(aB1[2*q],     kb1, v01);
                FMA2(aB0[2*q + 1], kb0, v23);
                FMA2(aB1[2*q + 1], kb1, v23);
            }
            unsigned long long vt;                         // cols (32,33): only K-half live
            asm volatile("ld.shared.b64 %0, [%1];" : "=l"(vt) : "r"(srow + 128));
            FMA2(aK0[16], ka0, vt);
            FMA2(aK1[16], ka1, vt);
        }
        // ---- f1 = 2j+1 ----
        {
            srow += NCOL_PAD * 4;
            unsigned long long ka0, kb0, ka1, kb1;
            PACK2(ka0, c0.z); PACK2(kb0, c0.w);
            PACK2(ka1, c1.z); PACK2(kb1, c1.w);
            #pragma unroll
            for (int q = 0; q < 8; q++) {
                unsigned long long v01, v23;
                asm volatile("ld.shared.v2.b64 {%0, %1}, [%2];"
                             : "=l"(v01), "=l"(v23) : "r"(srow + q * 16));
                FMA2(aK0[2*q],     ka0, v01);
                FMA2(aK1[2*q],     ka1, v01);
                FMA2(aK0[2*q + 1], ka0, v23);
                FMA2(aK1[2*q + 1], ka1, v23);
                FMA2(aB0[2*q],     kb0, v01);
                FMA2(aB1[2*q],     kb1, v01);
                FMA2(aB0[2*q + 1], kb0, v23);
                FMA2(aB1[2*q + 1], kb1, v23);
            }
            unsigned long long vt;
            asm volatile("ld.shared.b64 %0, [%1];" : "=l"(vt) : "r"(srow + 128));
            FMA2(aK0[16], ka0, vt);
            FMA2(aK1[16], ka1, vt);
        }

        c0 = n0; c1 = n1; n0 = p0; n1 = p1;                // rotate pipeline
    }

    // ---- Epilogue: seg s0+i gets aK[pair of j=i+1] + aB[pair of j=i] ----
    float* o0 = out + (size_t)b * L_OUT + (size_t)s0 * 256 + tid;
    #pragma unroll
    for (int i = 0; i < NSEG; i++) {
        int s = s0 + i;
        if (s < NSEG_TOTAL) {
            int jk = i + 1;
            unsigned uK0 = (jk & 1) ? (unsigned)(aK0[jk >> 1] >> 32) : (unsigned)aK0[jk >> 1];
            unsigned uK1 = (jk & 1) ? (unsigned)(aK1[jk >> 1] >> 32) : (unsigned)aK1[jk >> 1];
            unsigned uB0 = (i  & 1) ? (unsigned)(aB0[i  >> 1] >> 32) : (unsigned)aB0[i  >> 1];
            unsigned uB1 = (i  & 1) ? (unsigned)(aB1[i  >> 1] >> 32) : (unsigned)aB1[i  >> 1];
            o0[(size_t)i * 256]       = __uint_as_float(uK0) + __uint_as_float(uB0);
            o0[(size_t)i * 256 + 128] = __uint_as_float(uK1) + __uint_as_float(uB1);
        }
    }
}

extern "C" void kernel_launch(void* const* d_in, const int* in_sizes, int n_in,
                              void* d_out, int out_size)
{
    const float* spec    = (const float*)d_in[0];   // [16,1,256,4096]
    const float* kernels = (const float*)d_in[1];   // [512,256]
    float* out = (float*)d_out;                     // [16,1048832]

    transpose_scale_kernel<<<128, 256>>>(kernels);  // 32768 threads

    dim3 grid((NSEG_TOTAL + NSEG - 1) / NSEG, 16);  // (129, 16)
    imdct_main_kernel<<<grid, 128>>>(spec, out);
}

// round 5
// speedup vs baseline: 1.6484x; 1.6484x over previous
#include <cuda_runtime.h>
#include <cstdint>
#include <math.h>

// IMDCT with basis-symmetry-halved GEMM (FFMA2 path).
//
// Identity of the unwindowed basis c[t,f] = cos(pi/512*(2t+1+256)(f+0.5)):
//   c[255-t,f] = -c[t,f]   (t in [0,256))
//   c[767-t,f] =  c[t,f]   (t in [384,512))
// => only rows 128..383 needed. Reduced weights kr[j][f] = kernels[128+j][f]/(128*win[128+j]).
// z_col[j] = sum_f kr[j][f] * spec[b,f,col]. Epilogue:
//   out[b, s*256+k] = win[k]  * (k<128 ? -z_s[127-k]   : z_s[k-128])
//                   + win[k+256]*(k<128 ?  z_{s-1}[k+128] : z_{s-1}[383-k])
//
// Block = 64 threads, owns NSEG=32 segments (34 spec cols incl. halo, zero-padded edges).
// Thread owns 4 z-rows {t, t+64, t+128, t+192} x 17 col-pairs, packed fma.rn.f32x2.
// D-tile staged transposed in smem (Dt[c][j], stride 257 -> conflict-free), then windowed out.

#define NFREQ    256
#define TFRAMES  4096
#define NSEG     32
#define COLPAD   36         // 34 used spec cols + pad
#define LOUT     1048832
#define DSTR     257        // Dt row stride (words), odd -> conflict-free j-consecutive access

#define FMA2(acc, a, v) \
    asm("fma.rn.f32x2 %0, %1, %2, %0;" : "+l"(acc) : "l"(a), "l"(v))
#define PACK2(dst, x) \
    asm("mov.b64 %0, {%1, %1};" : "=l"(dst) : "r"(__float_as_uint(x)))

// Reduced weights: g_kt4[f*64 + t] = { kr(t), kr(t+64), kr(t+128), kr(t+192) }(f).
// One pad f-row for depth-1 prefetch overrun.
__device__ float4 g_kt4[257 * 64];
__device__ float  g_win[512];

static __device__ __forceinline__ float win_of(int t) {
    return sinf((float)M_PI * (float)(2 * t + 1) * (1.0f / 1024.0f));
}

__global__ void prep_kernel(const float* __restrict__ kernels)
{
    int idx = blockIdx.x * blockDim.x + threadIdx.x;   // 16384 threads
    if (idx < 512) g_win[idx] = win_of(idx);
    int f = idx & 255;
    int t = idx >> 8;                                  // 0..63
    const float s = 1.0f / 128.0f;
    float4 w;
    w.x = s * kernels[(128 + t      ) * 256 + f] / win_of(128 + t      );
    w.y = s * kernels[(128 + t +  64) * 256 + f] / win_of(128 + t +  64);
    w.z = s * kernels[(128 + t + 128) * 256 + f] / win_of(128 + t + 128);
    w.w = s * kernels[(128 + t + 192) * 256 + f] / win_of(128 + t + 192);
    g_kt4[f * 64 + t] = w;
}

__global__ __launch_bounds__(64, 6)
void imdct_main_kernel(const float* __restrict__ spec, float* __restrict__ out)
{
    __shared__ float sm[NFREQ * COLPAD];               // 36,864 B; reused as Dt[34][DSTR]

    const int tid = threadIdx.x;                       // 0..63
    const int b   = blockIdx.y;
    const int s0  = blockIdx.x * NSEG;

    // ---- Load spec columns c = s0-1 .. s0+32 (zero-fill edges / pad) ----
    const float* specB = spec + (size_t)b * NFREQ * TFRAMES;
    for (int idx = tid; idx < NFREQ * COLPAD; idx += 64) {
        int f = idx / COLPAD;
        int j = idx - f * COLPAD;
        int c = s0 - 1 + j;
        float v = 0.0f;
        if (j < 34 && c >= 0 && c < TFRAMES)
            v = specB[(size_t)f * TFRAMES + c];
        sm[idx] = v;
    }
    __syncthreads();

    // ---- Accumulators: 4 z-rows x 17 col-pairs ----
    unsigned long long acc[4][17];
    #pragma unroll
    for (int m = 0; m < 4; m++)
        #pragma unroll
        for (int p = 0; p < 17; p++) acc[m][p] = 0ull;

    const uint32_t sbase = (uint32_t)__cvta_generic_to_shared(sm);
    const float4* __restrict__ wp = g_kt4 + tid;

    float4 wc = wp[0];                                 // depth-1 prefetch

    #pragma unroll 1
    for (int f = 0; f < NFREQ; f++) {
        float4 wn = wp[(f + 1) * 64];

        unsigned long long w2[4];
        PACK2(w2[0], wc.x); PACK2(w2[1], wc.y);
        PACK2(w2[2], wc.z); PACK2(w2[3], wc.w);

        uint32_t srow = sbase + (uint32_t)(f * (COLPAD * 4));
        #pragma unroll
        for (int q = 0; q < 8; q++) {
            unsigned long long v01, v23;               // col pairs (4q,4q+1), (4q+2,4q+3)
            asm volatile("ld.shared.v2.b64 {%0, %1}, [%2];"
                         : "=l"(v01), "=l"(v23) : "r"(srow + q * 16));
            FMA2(acc[0][2*q], w2[0], v01);  FMA2(acc[0][2*q+1], w2[0], v23);
            FMA2(acc[1][2*q], w2[1], v01);  FMA2(acc[1][2*q+1], w2[1], v23);
            FMA2(acc[2][2*q], w2[2], v01);  FMA2(acc[2][2*q+1], w2[2], v23);
            FMA2(acc[3][2*q], w2[3], v01);  FMA2(acc[3][2*q+1], w2[3], v23);
        }
        unsigned long long vt;                         // tail pair: cols (32,33)
        asm volatile("ld.shared.b64 %0, [%1];" : "=l"(vt) : "r"(srow + 128));
        FMA2(acc[0][16], w2[0], vt);
        FMA2(acc[1][16], w2[1], vt);
        FMA2(acc[2][16], w2[2], vt);
        FMA2(acc[3][16], w2[3], vt);

        wc = wn;
    }

    // ---- Stage D transposed: Dt[c][j] = z_col_c[j], c=0..33 ----
    __syncthreads();                                   // done reading spec from sm
    #pragma unroll
    for (int m = 0; m < 4; m++) {
        int j = tid + 64 * m;
        #pragma unroll
        for (int p = 0; p < 17; p++) {
            unsigned long long a = acc[m][p];
            sm[(2 * p)     * DSTR + j] = __uint_as_float((unsigned)a);
            sm[(2 * p + 1) * DSTR + j] = __uint_as_float((unsigned)(a >> 32));
        }
    }
    __syncthreads();

    // ---- Windowed overlap-add epilogue ----
    float* ob = out + (size_t)b * LOUT;
    #pragma unroll
    for (int g = 0; g < 4; g++) {
        int k  = tid + 64 * g;                         // 0..255
        bool lo = (k < 128);
        int jA = lo ? (127 - k) : (k - 128);
        int jB = lo ? (k + 128) : (383 - k);
        float wA = __ldg(&g_win[k]) * (lo ? -1.0f : 1.0f);
        float wB = __ldg(&g_win[k + 256]);
        #pragma unroll
        for (int i = 0; i < NSEG; i++) {
            int s = s0 + i;
            if (s <= 4096) {
                float a  = sm[(i + 1) * DSTR + jA];    // z_s
                float bv = sm[i * DSTR + jB];          // z_{s-1}
                ob[(size_t)s * 256 + k] = wA * a + wB * bv;
            }
        }
    }
}

extern "C" void kernel_launch(void* const* d_in, const int* in_sizes, int n_in,
                              void* d_out, int out_size)
{
    const float* spec    = (const float*)d_in[0];   // [16,1,256,4096]
    const float* kernels = (const float*)d_in[1];   // [512,256]
    float* out = (float*)d_out;                     // [16,1048832]

    prep_kernel<<<64, 256>>>(kernels);              // 16384 threads

    dim3 grid((4097 + NSEG - 1) / NSEG, 16);        // (129, 16)
    imdct_main_kernel<<<grid, 64>>>(spec, out);
}